// round 2
// baseline (speedup 1.0000x reference)
#include <cuda_runtime.h>
#include <math_constants.h>

// ---------------- problem constants ----------------
#define S_LEN 97
#define B_DIM 256
#define W_DIM 1024
#define H_NUM 16
#define HD_DIM 64
#define M_ROWS (S_LEN * B_DIM)   // 24832
#define HALF_W (W_DIM / 2)       // 512

// ---------------- scratch (device globals; no runtime alloc) ----------------
__device__ float g_q1[(size_t)M_ROWS * W_DIM];
__device__ float g_k1[(size_t)M_ROWS * W_DIM];
__device__ float g_v2[(size_t)M_ROWS * W_DIM];
__device__ float g_q2[(size_t)M_ROWS * W_DIM];
__device__ float g_k2[(size_t)M_ROWS * W_DIM];
__device__ float g_o [(size_t)M_ROWS * W_DIM];
__device__ float g_wcv[(size_t)W_DIM * W_DIM];   // Wv @ v_w
__device__ float g_wco[(size_t)W_DIM * W_DIM];   // out_w @ mha_out_w
__device__ float g_bcv[W_DIM];
__device__ float g_bco[W_DIM];
__device__ float g_cos[S_LEN * HALF_W];
__device__ float g_sin[S_LEN * HALF_W];

// ---------------- rope tables ----------------
__global__ void rope_kernel(float* __restrict__ rc, float* __restrict__ rs) {
    int i = blockIdx.x * blockDim.x + threadIdx.x;
    if (i >= S_LEN * HALF_W) return;
    int s = i / HALF_W, j = i % HALF_W;
    float inv = expf(-logf(10000.0f) * (2.0f * (float)j) / (float)W_DIM);
    float ang = (float)s * inv;
    rc[i] = cosf(ang);
    rs[i] = sinf(ang);
}

// bout[n] = badd[n] + dot(Wmat[n,:], bin)   (one warp per n)
__global__ void bias_combine(const float* __restrict__ Wmat, const float* __restrict__ bin,
                             const float* __restrict__ badd, float* __restrict__ bout) {
    int gw = (blockIdx.x * blockDim.x + threadIdx.x) >> 5;
    int lane = threadIdx.x & 31;
    if (gw >= W_DIM) return;
    float s = 0.f;
    const float* wr = Wmat + (size_t)gw * W_DIM;
    for (int t = lane; t < W_DIM; t += 32) s = fmaf(wr[t], bin[t], s);
    #pragma unroll
    for (int o = 16; o; o >>= 1) s += __shfl_xor_sync(0xffffffffu, s, o);
    if (lane == 0) bout[gw] = badd[gw] + s;
}

// ---------------- tiled fp32 GEMM, register-prefetch pipelined ----------------
// EPI: 0 = +bias, 1 = +bias then rotary.
// BLAYOUT: 0 = C = A[M,K] @ Wt[N,K]^T   (both K-contiguous)
//          1 = C = A[M,K] @ B[K,N]      (row-major x row-major)
// Tiles: 128x128x16, 256 threads, 8x8 per thread.
template<int EPI, int BLAYOUT>
__global__ __launch_bounds__(256, 2)
void sgemm_kernel(const float* __restrict__ A, const float* __restrict__ Bm,
                  const float* __restrict__ bias, float* __restrict__ C,
                  int M, int N, int K,
                  const float* __restrict__ rc, const float* __restrict__ rsn) {
    __shared__ float As[16][132];
    __shared__ float Bs[16][132];
    const int tid = threadIdx.x;
    const int bm = blockIdx.y * 128;
    const int bn = blockIdx.x * 128;
    const int ty = tid >> 4, tx = tid & 15;

    // per-thread staging coordinates (fixed across tiles)
    const int ar0 = tid >> 2,         ac0 = (tid & 3) << 2;          // A, l=0
    const int ar1 = (tid + 256) >> 2, ac1 = ((tid + 256) & 3) << 2;  // A, l=1
    // B coords depend on layout
    const int b0r = (BLAYOUT == 0) ? (tid >> 2)         : (tid >> 5);
    const int b0c = (BLAYOUT == 0) ? ((tid & 3) << 2)   : ((tid & 31) << 2);
    const int b1r = (BLAYOUT == 0) ? ((tid + 256) >> 2) : ((tid + 256) >> 5);
    const int b1c = (BLAYOUT == 0) ? (((tid + 256) & 3) << 2) : (((tid + 256) & 31) << 2);

    float acc[8][8];
    #pragma unroll
    for (int i = 0; i < 8; i++)
        #pragma unroll
        for (int j = 0; j < 8; j++) acc[i][j] = 0.f;

    float4 pa0, pa1, pb0, pb1;

    // ---- tile load helpers (macro-style via lambdas) ----
    auto load_tile = [&](int k0) {
        pa0 = *(const float4*)(A + (size_t)(bm + ar0) * K + k0 + ac0);
        pa1 = *(const float4*)(A + (size_t)(bm + ar1) * K + k0 + ac1);
        if (BLAYOUT == 0) {
            pb0 = *(const float4*)(Bm + (size_t)(bn + b0r) * K + k0 + b0c);
            pb1 = *(const float4*)(Bm + (size_t)(bn + b1r) * K + k0 + b1c);
        } else {
            pb0 = *(const float4*)(Bm + (size_t)(k0 + b0r) * N + bn + b0c);
            pb1 = *(const float4*)(Bm + (size_t)(k0 + b1r) * N + bn + b1c);
        }
    };
    auto store_tile = [&]() {
        As[ac0 + 0][ar0] = pa0.x; As[ac0 + 1][ar0] = pa0.y;
        As[ac0 + 2][ar0] = pa0.z; As[ac0 + 3][ar0] = pa0.w;
        As[ac1 + 0][ar1] = pa1.x; As[ac1 + 1][ar1] = pa1.y;
        As[ac1 + 2][ar1] = pa1.z; As[ac1 + 3][ar1] = pa1.w;
        if (BLAYOUT == 0) {
            Bs[b0c + 0][b0r] = pb0.x; Bs[b0c + 1][b0r] = pb0.y;
            Bs[b0c + 2][b0r] = pb0.z; Bs[b0c + 3][b0r] = pb0.w;
            Bs[b1c + 0][b1r] = pb1.x; Bs[b1c + 1][b1r] = pb1.y;
            Bs[b1c + 2][b1r] = pb1.z; Bs[b1c + 3][b1r] = pb1.w;
        } else {
            *(float4*)&Bs[b0r][b0c] = pb0;
            *(float4*)&Bs[b1r][b1c] = pb1;
        }
    };
    auto compute_tile = [&]() {
        #pragma unroll
        for (int kk = 0; kk < 16; kk++) {
            float a[8], b[8];
            #pragma unroll
            for (int i = 0; i < 8; i++) a[i] = As[kk][ty * 8 + i];
            #pragma unroll
            for (int j = 0; j < 8; j++) b[j] = Bs[kk][tx * 8 + j];
            #pragma unroll
            for (int i = 0; i < 8; i++)
                #pragma unroll
                for (int j = 0; j < 8; j++)
                    acc[i][j] = fmaf(a[i], b[j], acc[i][j]);
        }
    };

    // ---- pipelined main loop ----
    load_tile(0);
    store_tile();
    __syncthreads();
    for (int k0 = 16; k0 < K; k0 += 16) {
        load_tile(k0);        // LDGs in flight while computing below
        compute_tile();
        __syncthreads();      // everyone done reading current tiles
        store_tile();
        __syncthreads();      // tiles visible
    }
    compute_tile();

    // ---- epilogue ----
    #pragma unroll
    for (int i = 0; i < 8; i++) {
        int m = bm + ty * 8 + i;
        int srow = (EPI == 1) ? (m / B_DIM) : 0;
        #pragma unroll
        for (int j = 0; j < 8; j += 2) {
            int n = bn + tx * 8 + j;   // even
            float v0 = acc[i][j]     + (bias ? bias[n]     : 0.f);
            float v1 = acc[i][j + 1] + (bias ? bias[n + 1] : 0.f);
            if (EPI == 1) {
                int pj = n >> 1;
                float c  = rc [srow * HALF_W + pj];
                float sn = rsn[srow * HALF_W + pj];
                float oe = v0 * c - v1 * sn;
                float oo = v0 * sn + v1 * c;
                v0 = oe; v1 = oo;
            }
            C[(size_t)m * N + n]     = v0;
            C[(size_t)m * N + n + 1] = v1;
        }
    }
}

// ---------------- attention: one block per (b,h) ----------------
// smem: Kst[64][97] (d-major, transposed), Vs[97][64], qs[4][64]
#define ATT_SMEM_BYTES ((64 * S_LEN + S_LEN * 64 + 4 * 64) * 4)

__global__ __launch_bounds__(128)
void attention_kernel(const float* __restrict__ q, const float* __restrict__ k,
                      const float* __restrict__ v, const float* __restrict__ mask,
                      float* __restrict__ o) {
    extern __shared__ float sm[];
    float* Kst = sm;                       // [64][97]
    float* Vs  = sm + 64 * S_LEN;          // [97][64]
    float* qs  = Vs + S_LEN * 64;          // [4][64]

    const int bh = blockIdx.x;
    const int b = bh >> 4;                 // /H_NUM
    const int h = bh & (H_NUM - 1);
    const int tid = threadIdx.x, warp = tid >> 5, lane = tid & 31;
    const size_t hoff = (size_t)h * HD_DIM;

    // stage K (transposed) and V
    for (int i = tid; i < S_LEN * 16; i += 128) {
        int s = i >> 4, c4 = (i & 15) << 2;
        size_t goff = ((size_t)(s * B_DIM + b)) * W_DIM + hoff + c4;
        float4 kv = *(const float4*)(k + goff);
        Kst[(c4 + 0) * S_LEN + s] = kv.x;
        Kst[(c4 + 1) * S_LEN + s] = kv.y;
        Kst[(c4 + 2) * S_LEN + s] = kv.z;
        Kst[(c4 + 3) * S_LEN + s] = kv.w;
        *(float4*)&Vs[s * 64 + c4] = *(const float4*)(v + goff);
    }
    __syncthreads();

    for (int iq = warp; iq < S_LEN; iq += 4) {
        if (lane < 16) {
            size_t goff = ((size_t)(iq * B_DIM + b)) * W_DIM + hoff + lane * 4;
            *(float4*)&qs[warp * 64 + lane * 4] = *(const float4*)(q + goff);
        }
        __syncwarp();

        // scores: lane owns keys lane, lane+32, lane+64 (+ key 96 via lane 0)
        float d0 = 0.f, d1 = 0.f, d2 = 0.f, d3 = 0.f;
        #pragma unroll 8
        for (int d = 0; d < 64; d++) {
            float qd = qs[warp * 64 + d];
            const float* kr = Kst + d * S_LEN;
            d0 = fmaf(qd, kr[lane],      d0);
            d1 = fmaf(qd, kr[lane + 32], d1);
            d2 = fmaf(qd, kr[lane + 64], d2);
            d3 = fmaf(qd, kr[96],        d3);   // only lane 0's value used
        }
        const float scale = 0.125f;
        const float* mrow = mask + iq * S_LEN;
        float s0 = d0 * scale + mrow[lane];
        float s1 = d1 * scale + mrow[lane + 32];
        float s2 = d2 * scale + mrow[lane + 64];
        float s3 = (lane == 0) ? (d3 * scale + mrow[96]) : -CUDART_INF_F;

        float mx = fmaxf(fmaxf(s0, s1), fmaxf(s2, s3));
        #pragma unroll
        for (int off = 16; off; off >>= 1)
            mx = fmaxf(mx, __shfl_xor_sync(0xffffffffu, mx, off));

        float e0 = expf(s0 - mx), e1 = expf(s1 - mx), e2 = expf(s2 - mx);
        float e3 = (lane == 0) ? expf(s3 - mx) : 0.f;
        float ssum = e0 + e1 + e2 + e3;
        #pragma unroll
        for (int off = 16; off; off >>= 1)
            ssum += __shfl_xor_sync(0xffffffffu, ssum, off);
        float inv = 1.0f / ssum;

        // o[d] = sum_j p_j * V[j][d]; probs redistributed via shuffle
        float a0 = 0.f, a1 = 0.f;
        for (int jl = 0; jl < 32; jl++) {
            float p0 = __shfl_sync(0xffffffffu, e0, jl);
            float p1 = __shfl_sync(0xffffffffu, e1, jl);
            float p2 = __shfl_sync(0xffffffffu, e2, jl);
            const float* v0r = Vs + jl * 64;
            const float* v1r = Vs + (jl + 32) * 64;
            const float* v2r = Vs + (jl + 64) * 64;
            a0 = fmaf(p0, v0r[lane],      a0);
            a1 = fmaf(p0, v0r[lane + 32], a1);
            a0 = fmaf(p1, v1r[lane],      a0);
            a1 = fmaf(p1, v1r[lane + 32], a1);
            a0 = fmaf(p2, v2r[lane],      a0);
            a1 = fmaf(p2, v2r[lane + 32], a1);
        }
        {
            float p3 = __shfl_sync(0xffffffffu, e3, 0);
            const float* v3r = Vs + 96 * 64;
            a0 = fmaf(p3, v3r[lane],      a0);
            a1 = fmaf(p3, v3r[lane + 32], a1);
        }

        float* op = o + ((size_t)(iq * B_DIM + b)) * W_DIM + hoff;
        op[lane]      = a0 * inv;
        op[lane + 32] = a1 * inv;
        __syncwarp();   // qs rewritten next iteration
    }
}

// ---------------- launch ----------------
extern "C" void kernel_launch(void* const* d_in, const int* in_sizes, int n_in,
                              void* d_out, int out_size) {
    const float* tensor = (const float*)d_in[0];
    const float* mask   = (const float*)d_in[1];
    const float* q_w    = (const float*)d_in[2];
    const float* q_b    = (const float*)d_in[3];
    const float* k_w    = (const float*)d_in[4];
    const float* k_b    = (const float*)d_in[5];
    const float* v_w    = (const float*)d_in[6];
    const float* v_b    = (const float*)d_in[7];
    const float* in_w   = (const float*)d_in[8];   // [3W, W]
    const float* in_b   = (const float*)d_in[9];   // [3W]
    const float* mo_w   = (const float*)d_in[10];
    const float* mo_b   = (const float*)d_in[11];
    const float* out_w  = (const float*)d_in[12];
    const float* out_b  = (const float*)d_in[13];
    float* out = (float*)d_out;

    float *q1, *k1, *v2, *q2, *k2, *ob, *wcv, *wco, *bcv, *bco, *rc, *rs;
    cudaGetSymbolAddress((void**)&q1,  g_q1);
    cudaGetSymbolAddress((void**)&k1,  g_k1);
    cudaGetSymbolAddress((void**)&v2,  g_v2);
    cudaGetSymbolAddress((void**)&q2,  g_q2);
    cudaGetSymbolAddress((void**)&k2,  g_k2);
    cudaGetSymbolAddress((void**)&ob,  g_o);
    cudaGetSymbolAddress((void**)&wcv, g_wcv);
    cudaGetSymbolAddress((void**)&wco, g_wco);
    cudaGetSymbolAddress((void**)&bcv, g_bcv);
    cudaGetSymbolAddress((void**)&bco, g_bco);
    cudaGetSymbolAddress((void**)&rc,  g_cos);
    cudaGetSymbolAddress((void**)&rs,  g_sin);

    const float* Wv = in_w + 2 * (size_t)W_DIM * W_DIM;
    const float* bv = in_b + 2 * W_DIM;

    // rope tables + combined weights/biases (small)
    rope_kernel<<<(S_LEN * HALF_W + 255) / 256, 256>>>(rc, rs);
    sgemm_kernel<0, 1><<<dim3(8, 8), 256>>>(Wv, v_w, nullptr, wcv,
                                            W_DIM, W_DIM, W_DIM, nullptr, nullptr);
    sgemm_kernel<0, 1><<<dim3(8, 8), 256>>>(out_w, mo_w, nullptr, wco,
                                            W_DIM, W_DIM, W_DIM, nullptr, nullptr);
    bias_combine<<<(W_DIM * 32) / 256, 256>>>(Wv, v_b, bv, bcv);
    bias_combine<<<(W_DIM * 32) / 256, 256>>>(out_w, mo_b, out_b, bco);

    dim3 big(W_DIM / 128, M_ROWS / 128);   // (8, 194)

    // stage 1: q/k projections fused with rotary; v path fully combined
    sgemm_kernel<1, 0><<<big, 256>>>(tensor, q_w, q_b, q1, M_ROWS, W_DIM, W_DIM, rc, rs);
    sgemm_kernel<1, 0><<<big, 256>>>(tensor, k_w, k_b, k1, M_ROWS, W_DIM, W_DIM, rc, rs);
    sgemm_kernel<0, 0><<<big, 256>>>(tensor, wcv, bcv, v2, M_ROWS, W_DIM, W_DIM, nullptr, nullptr);

    // stage 2: in_proj on rotated q/k
    sgemm_kernel<0, 0><<<big, 256>>>(q1, in_w, in_b, q2, M_ROWS, W_DIM, W_DIM, nullptr, nullptr);
    sgemm_kernel<0, 0><<<big, 256>>>(k1, in_w + (size_t)W_DIM * W_DIM, in_b + W_DIM, k2,
                                     M_ROWS, W_DIM, W_DIM, nullptr, nullptr);

    // attention
    cudaFuncSetAttribute(attention_kernel,
                         cudaFuncAttributeMaxDynamicSharedMemorySize, ATT_SMEM_BYTES);
    attention_kernel<<<B_DIM * H_NUM, 128, ATT_SMEM_BYTES>>>(q2, k2, v2, mask, ob);

    // fused output projection (mha_out then out combined)
    sgemm_kernel<0, 0><<<big, 256>>>(ob, wco, bco, out, M_ROWS, W_DIM, W_DIM, nullptr, nullptr);
}

// round 10
// speedup vs baseline: 1.6373x; 1.6373x over previous
#include <cuda_runtime.h>
#include <cuda_bf16.h>
#include <math_constants.h>

// ---------------- problem constants ----------------
#define S_LEN 97
#define B_DIM 256
#define W_DIM 1024
#define H_NUM 16
#define HD_DIM 64
#define M_ROWS (S_LEN * B_DIM)   // 24832
#define HALF_W (W_DIM / 2)       // 512

// ---------------- scratch (device globals; no runtime alloc) ----------------
__device__ float g_q1[(size_t)M_ROWS * W_DIM];
__device__ float g_k1[(size_t)M_ROWS * W_DIM];
__device__ float g_v2[(size_t)M_ROWS * W_DIM];
__device__ float g_q2[(size_t)M_ROWS * W_DIM];
__device__ float g_k2[(size_t)M_ROWS * W_DIM];
__device__ float g_o [(size_t)M_ROWS * W_DIM];
__device__ float g_wcv[(size_t)W_DIM * W_DIM];   // Wv @ v_w
__device__ float g_wco[(size_t)W_DIM * W_DIM];   // out_w @ mha_out_w
__device__ float g_bcv[W_DIM];
__device__ float g_bco[W_DIM];
__device__ float g_cos[S_LEN * HALF_W];
__device__ float g_sin[S_LEN * HALF_W];

// ---------------- rope tables ----------------
__global__ void rope_kernel(float* __restrict__ rc, float* __restrict__ rs) {
    int i = blockIdx.x * blockDim.x + threadIdx.x;
    if (i >= S_LEN * HALF_W) return;
    int s = i / HALF_W, j = i % HALF_W;
    float inv = expf(-logf(10000.0f) * (2.0f * (float)j) / (float)W_DIM);
    float ang = (float)s * inv;
    rc[i] = cosf(ang);
    rs[i] = sinf(ang);
}

// bout[n] = badd[n] + dot(Wmat[n,:], bin)
__global__ void bias_combine(const float* __restrict__ Wmat, const float* __restrict__ bin,
                             const float* __restrict__ badd, float* __restrict__ bout) {
    int gw = (blockIdx.x * blockDim.x + threadIdx.x) >> 5;
    int lane = threadIdx.x & 31;
    if (gw >= W_DIM) return;
    float s = 0.f;
    const float* wr = Wmat + (size_t)gw * W_DIM;
    for (int t = lane; t < W_DIM; t += 32) s = fmaf(wr[t], bin[t], s);
    #pragma unroll
    for (int o = 16; o; o >>= 1) s += __shfl_xor_sync(0xffffffffu, s, o);
    if (lane == 0) bout[gw] = badd[gw] + s;
}

// ---------------- fp32 GEMM (kept for the two exact weight combines) ----------
__global__ __launch_bounds__(256, 2)
void sgemm_nn_kernel(const float* __restrict__ A, const float* __restrict__ Bm,
                     float* __restrict__ C, int M, int N, int K) {
    __shared__ float As[16][132];
    __shared__ float Bs[16][132];
    const int tid = threadIdx.x;
    const int bm = blockIdx.y * 128, bn = blockIdx.x * 128;
    const int ty = tid >> 4, tx = tid & 15;
    float acc[8][8];
    #pragma unroll
    for (int i = 0; i < 8; i++)
        #pragma unroll
        for (int j = 0; j < 8; j++) acc[i][j] = 0.f;

    for (int k0 = 0; k0 < K; k0 += 16) {
        #pragma unroll
        for (int l = 0; l < 2; l++) {
            int f = tid + l * 256;
            int r = f >> 2, c = (f & 3) << 2;
            float4 v = *(const float4*)(A + (size_t)(bm + r) * K + k0 + c);
            As[c + 0][r] = v.x; As[c + 1][r] = v.y;
            As[c + 2][r] = v.z; As[c + 3][r] = v.w;
            int r2 = f >> 5, c2 = (f & 31) << 2;
            *(float4*)&Bs[r2][c2] = *(const float4*)(Bm + (size_t)(k0 + r2) * N + bn + c2);
        }
        __syncthreads();
        #pragma unroll
        for (int kk = 0; kk < 16; kk++) {
            float a[8], b[8];
            #pragma unroll
            for (int i = 0; i < 8; i++) a[i] = As[kk][ty * 8 + i];
            #pragma unroll
            for (int j = 0; j < 8; j++) b[j] = Bs[kk][tx * 8 + j];
            #pragma unroll
            for (int i = 0; i < 8; i++)
                #pragma unroll
                for (int j = 0; j < 8; j++)
                    acc[i][j] = fmaf(a[i], b[j], acc[i][j]);
        }
        __syncthreads();
    }
    #pragma unroll
    for (int i = 0; i < 8; i++)
        #pragma unroll
        for (int j = 0; j < 4; j++)
            *(float2*)(C + (size_t)(bm + ty * 8 + i) * N + bn + tx * 8 + j * 2)
                = make_float2(acc[i][j * 2], acc[i][j * 2 + 1]);
}

// ---------------- split-bf16 tensor-core GEMM, double-buffered ----------------
// C = A[M,K] @ Wt[N,K]^T + bias, optional rotary epilogue (EPI=1).
// Split: C ~= Ah.Bh + Ah.Bl + Al.Bh  (fp32 accum), err ~1e-5.
// Block tile 128x64, 8 warps (2x4), warp tile 64x16.
// K-tile 32, register-prefetch + smem ping-pong (one barrier per K-tile).

__device__ __forceinline__ unsigned smem_u32(const void* p) {
    return static_cast<unsigned>(__cvta_generic_to_shared(p));
}
__device__ __forceinline__ void ldsm_x4(unsigned* r, unsigned addr) {
    asm volatile("ldmatrix.sync.aligned.m8n8.x4.shared.b16 {%0,%1,%2,%3}, [%4];"
                 : "=r"(r[0]), "=r"(r[1]), "=r"(r[2]), "=r"(r[3]) : "r"(addr));
}
__device__ __forceinline__ void ldsm_x2(unsigned* r, unsigned addr) {
    asm volatile("ldmatrix.sync.aligned.m8n8.x2.shared.b16 {%0,%1}, [%2];"
                 : "=r"(r[0]), "=r"(r[1]) : "r"(addr));
}
__device__ __forceinline__ void mma16816(float* c, const unsigned* a, const unsigned* b) {
    asm volatile(
        "mma.sync.aligned.m16n8k16.row.col.f32.bf16.bf16.f32 "
        "{%0,%1,%2,%3}, {%4,%5,%6,%7}, {%8,%9}, {%0,%1,%2,%3};"
        : "+f"(c[0]), "+f"(c[1]), "+f"(c[2]), "+f"(c[3])
        : "r"(a[0]), "r"(a[1]), "r"(a[2]), "r"(a[3]), "r"(b[0]), "r"(b[1]));
}

#define KTILE 32
#define APAD 40                       // bf16 row stride (80 B)
#define AH_OFF 0                      // [128][APAD]
#define AL_OFF (128 * APAD)           // [128][APAD]
#define BH_OFF (256 * APAD)           // [64][APAD]
#define BL_OFF (320 * APAD)           // [64][APAD]
#define BUF_ELEMS (384 * APAD)        // 15360 bf16 = 30720 B per buffer
#define GEMM_SMEM_BYTES (2 * BUF_ELEMS * 2)   // 61440 B

template<int EPI>
__global__ __launch_bounds__(256, 2)
void gemm_bf16s_kernel(const float* __restrict__ A, const float* __restrict__ Wt,
                       const float* __restrict__ bias, float* __restrict__ C,
                       int M, int N, int K,
                       const float* __restrict__ rc, const float* __restrict__ rsn) {
    extern __shared__ __align__(16) __nv_bfloat16 smem_dyn[];

    const int tid  = threadIdx.x;
    const int lane = tid & 31;
    const int warp = tid >> 5;
    const int wm   = (warp >> 2) * 64;   // warp m-origin in tile
    const int wn   = (warp & 3) * 16;    // warp n-origin in tile
    const int bm   = blockIdx.y * 128;
    const int bn   = blockIdx.x * 64;

    // per-thread staging coords
    const int ar = tid >> 1;
    const int ac = (tid & 1) * 16;                 // + i*4, i=0..3
    const int br = tid >> 2;
    const int bc = (tid & 3) * 8;                  // + i*4, i=0..1

    float acc[4][2][4];
    #pragma unroll
    for (int i = 0; i < 4; i++)
        #pragma unroll
        for (int j = 0; j < 2; j++)
            #pragma unroll
            for (int t = 0; t < 4; t++) acc[i][j][t] = 0.f;

    float4 pa[4], pb[2];

    auto load_tile = [&](int k0) {
        #pragma unroll
        for (int i = 0; i < 4; i++)
            pa[i] = *(const float4*)(A + (size_t)(bm + ar) * K + k0 + ac + i * 4);
        #pragma unroll
        for (int i = 0; i < 2; i++)
            pb[i] = *(const float4*)(Wt + (size_t)(bn + br) * K + k0 + bc + i * 4);
    };
    auto store_tile = [&](int par) {
        __nv_bfloat16* buf = smem_dyn + par * BUF_ELEMS;
        __nv_bfloat16* sAh = buf + AH_OFF + ar * APAD;
        __nv_bfloat16* sAl = buf + AL_OFF + ar * APAD;
        __nv_bfloat16* sBh = buf + BH_OFF + br * APAD;
        __nv_bfloat16* sBl = buf + BL_OFF + br * APAD;
        #pragma unroll
        for (int i = 0; i < 4; i++) {
            const float x[4] = {pa[i].x, pa[i].y, pa[i].z, pa[i].w};
            #pragma unroll
            for (int j = 0; j < 4; j++) {
                __nv_bfloat16 h = __float2bfloat16_rn(x[j]);
                sAh[ac + i * 4 + j] = h;
                sAl[ac + i * 4 + j] = __float2bfloat16_rn(x[j] - __bfloat162float(h));
            }
        }
        #pragma unroll
        for (int i = 0; i < 2; i++) {
            const float x[4] = {pb[i].x, pb[i].y, pb[i].z, pb[i].w};
            #pragma unroll
            for (int j = 0; j < 4; j++) {
                __nv_bfloat16 h = __float2bfloat16_rn(x[j]);
                sBh[bc + i * 4 + j] = h;
                sBl[bc + i * 4 + j] = __float2bfloat16_rn(x[j] - __bfloat162float(h));
            }
        }
    };
    auto compute_tile = [&](int par) {
        const __nv_bfloat16* buf = smem_dyn + par * BUF_ELEMS;
        #pragma unroll
        for (int kk = 0; kk < KTILE; kk += 16) {
            unsigned bh[2][2], bl[2][2];
            #pragma unroll
            for (int nf = 0; nf < 2; nf++) {
                int r = wn + nf * 8 + (lane & 7);
                int c = kk + ((lane >> 3) & 1) * 8;
                ldsm_x2(bh[nf], smem_u32(buf + BH_OFF + r * APAD + c));
                ldsm_x2(bl[nf], smem_u32(buf + BL_OFF + r * APAD + c));
            }
            #pragma unroll
            for (int mf = 0; mf < 4; mf++) {
                int r = wm + mf * 16 + (lane & 15);
                int c = kk + (lane >> 4) * 8;
                unsigned ah[4], al[4];
                ldsm_x4(ah, smem_u32(buf + AH_OFF + r * APAD + c));
                ldsm_x4(al, smem_u32(buf + AL_OFF + r * APAD + c));
                #pragma unroll
                for (int nf = 0; nf < 2; nf++) {
                    mma16816(acc[mf][nf], ah, bh[nf]);
                    mma16816(acc[mf][nf], ah, bl[nf]);
                    mma16816(acc[mf][nf], al, bh[nf]);
                }
            }
        }
    };

    // ---- ping-pong main loop: ONE barrier per K-tile ----
    int par = 0;
    load_tile(0);
    store_tile(par);
    __syncthreads();
    for (int k0 = KTILE; k0 < K; k0 += KTILE) {
        load_tile(k0);           // prefetch (LDGs overlap compute below)
        compute_tile(par);       // read buffer par
        store_tile(par ^ 1);     // write other buffer (no readers yet)
        __syncthreads();         // all reads of par done; par^1 visible
        par ^= 1;
    }
    compute_tile(par);

    // epilogue: bias (+rotary), fragment-mapped
    #pragma unroll
    for (int mf = 0; mf < 4; mf++) {
        #pragma unroll
        for (int nf = 0; nf < 2; nf++) {
            int n = bn + wn + nf * 8 + 2 * (lane & 3);
            float b0 = bias[n], b1 = bias[n + 1];
            #pragma unroll
            for (int half = 0; half < 2; half++) {
                int m = bm + wm + mf * 16 + (lane >> 2) + half * 8;
                float v0 = acc[mf][nf][half * 2 + 0] + b0;
                float v1 = acc[mf][nf][half * 2 + 1] + b1;
                if (EPI == 1) {
                    int srow = m >> 8;           // m / B_DIM
                    int pj = n >> 1;
                    float co = rc [srow * HALF_W + pj];
                    float sn = rsn[srow * HALF_W + pj];
                    float oe = v0 * co - v1 * sn;
                    float oo = v0 * sn + v1 * co;
                    v0 = oe; v1 = oo;
                }
                *(float2*)(C + (size_t)m * N + n) = make_float2(v0, v1);
            }
        }
    }
}

// ---------------- attention: one block per (b,h) ----------------
#define ATT_SMEM_BYTES ((64 * S_LEN + S_LEN * 64 + 4 * 64) * 4)

__global__ __launch_bounds__(128)
void attention_kernel(const float* __restrict__ q, const float* __restrict__ k,
                      const float* __restrict__ v, const float* __restrict__ mask,
                      float* __restrict__ o) {
    extern __shared__ float sm[];
    float* Kst = sm;                       // [64][97]
    float* Vs  = sm + 64 * S_LEN;          // [97][64]
    float* qs  = Vs + S_LEN * 64;          // [4][64]

    const int bh = blockIdx.x;
    const int b = bh >> 4;
    const int h = bh & (H_NUM - 1);
    const int tid = threadIdx.x, warp = tid >> 5, lane = tid & 31;
    const size_t hoff = (size_t)h * HD_DIM;

    for (int i = tid; i < S_LEN * 16; i += 128) {
        int s = i >> 4, c4 = (i & 15) << 2;
        size_t goff = ((size_t)(s * B_DIM + b)) * W_DIM + hoff + c4;
        float4 kv = *(const float4*)(k + goff);
        Kst[(c4 + 0) * S_LEN + s] = kv.x;
        Kst[(c4 + 1) * S_LEN + s] = kv.y;
        Kst[(c4 + 2) * S_LEN + s] = kv.z;
        Kst[(c4 + 3) * S_LEN + s] = kv.w;
        *(float4*)&Vs[s * 64 + c4] = *(const float4*)(v + goff);
    }
    __syncthreads();

    for (int iq = warp; iq < S_LEN; iq += 4) {
        if (lane < 16) {
            size_t goff = ((size_t)(iq * B_DIM + b)) * W_DIM + hoff + lane * 4;
            *(float4*)&qs[warp * 64 + lane * 4] = *(const float4*)(q + goff);
        }
        __syncwarp();

        float d0 = 0.f, d1 = 0.f, d2 = 0.f, d3 = 0.f;
        #pragma unroll 8
        for (int d = 0; d < 64; d++) {
            float qd = qs[warp * 64 + d];
            const float* kr = Kst + d * S_LEN;
            d0 = fmaf(qd, kr[lane],      d0);
            d1 = fmaf(qd, kr[lane + 32], d1);
            d2 = fmaf(qd, kr[lane + 64], d2);
            d3 = fmaf(qd, kr[96],        d3);
        }
        const float scale = 0.125f;
        const float* mrow = mask + iq * S_LEN;
        float s0 = d0 * scale + mrow[lane];
        float s1 = d1 * scale + mrow[lane + 32];
        float s2 = d2 * scale + mrow[lane + 64];
        float s3 = (lane == 0) ? (d3 * scale + mrow[96]) : -CUDART_INF_F;

        float mx = fmaxf(fmaxf(s0, s1), fmaxf(s2, s3));
        #pragma unroll
        for (int off = 16; off; off >>= 1)
            mx = fmaxf(mx, __shfl_xor_sync(0xffffffffu, mx, off));

        float e0 = expf(s0 - mx), e1 = expf(s1 - mx), e2 = expf(s2 - mx);
        float e3 = (lane == 0) ? expf(s3 - mx) : 0.f;
        float ssum = e0 + e1 + e2 + e3;
        #pragma unroll
        for (int off = 16; off; off >>= 1)
            ssum += __shfl_xor_sync(0xffffffffu, ssum, off);
        float inv = 1.0f / ssum;

        float a0 = 0.f, a1 = 0.f;
        for (int jl = 0; jl < 32; jl++) {
            float p0 = __shfl_sync(0xffffffffu, e0, jl);
            float p1 = __shfl_sync(0xffffffffu, e1, jl);
            float p2 = __shfl_sync(0xffffffffu, e2, jl);
            const float* v0r = Vs + jl * 64;
            const float* v1r = Vs + (jl + 32) * 64;
            const float* v2r = Vs + (jl + 64) * 64;
            a0 = fmaf(p0, v0r[lane],      a0);
            a1 = fmaf(p0, v0r[lane + 32], a1);
            a0 = fmaf(p1, v1r[lane],      a0);
            a1 = fmaf(p1, v1r[lane + 32], a1);
            a0 = fmaf(p2, v2r[lane],      a0);
            a1 = fmaf(p2, v2r[lane + 32], a1);
        }
        {
            float p3 = __shfl_sync(0xffffffffu, e3, 0);
            const float* v3r = Vs + 96 * 64;
            a0 = fmaf(p3, v3r[lane],      a0);
            a1 = fmaf(p3, v3r[lane + 32], a1);
        }

        float* op = o + ((size_t)(iq * B_DIM + b)) * W_DIM + hoff;
        op[lane]      = a0 * inv;
        op[lane + 32] = a1 * inv;
        __syncwarp();
    }
}

// ---------------- launch ----------------
extern "C" void kernel_launch(void* const* d_in, const int* in_sizes, int n_in,
                              void* d_out, int out_size) {
    const float* tensor = (const float*)d_in[0];
    const float* mask   = (const float*)d_in[1];
    const float* q_w    = (const float*)d_in[2];
    const float* q_b    = (const float*)d_in[3];
    const float* k_w    = (const float*)d_in[4];
    const float* k_b    = (const float*)d_in[5];
    const float* v_w    = (const float*)d_in[6];
    const float* v_b    = (const float*)d_in[7];
    const float* in_w   = (const float*)d_in[8];   // [3W, W]
    const float* in_b   = (const float*)d_in[9];   // [3W]
    const float* mo_w   = (const float*)d_in[10];
    const float* mo_b   = (const float*)d_in[11];
    const float* out_w  = (const float*)d_in[12];
    const float* out_b  = (const float*)d_in[13];
    float* out = (float*)d_out;

    float *q1, *k1, *v2, *q2, *k2, *ob, *wcv, *wco, *bcv, *bco, *rc, *rs;
    cudaGetSymbolAddress((void**)&q1,  g_q1);
    cudaGetSymbolAddress((void**)&k1,  g_k1);
    cudaGetSymbolAddress((void**)&v2,  g_v2);
    cudaGetSymbolAddress((void**)&q2,  g_q2);
    cudaGetSymbolAddress((void**)&k2,  g_k2);
    cudaGetSymbolAddress((void**)&ob,  g_o);
    cudaGetSymbolAddress((void**)&wcv, g_wcv);
    cudaGetSymbolAddress((void**)&wco, g_wco);
    cudaGetSymbolAddress((void**)&bcv, g_bcv);
    cudaGetSymbolAddress((void**)&bco, g_bco);
    cudaGetSymbolAddress((void**)&rc,  g_cos);
    cudaGetSymbolAddress((void**)&rs,  g_sin);

    const float* Wv = in_w + 2 * (size_t)W_DIM * W_DIM;
    const float* bv = in_b + 2 * W_DIM;

    // allow 61440 B dynamic smem on both bf16-GEMM instantiations
    cudaFuncSetAttribute(gemm_bf16s_kernel<0>,
                         cudaFuncAttributeMaxDynamicSharedMemorySize, GEMM_SMEM_BYTES);
    cudaFuncSetAttribute(gemm_bf16s_kernel<1>,
                         cudaFuncAttributeMaxDynamicSharedMemorySize, GEMM_SMEM_BYTES);
    cudaFuncSetAttribute(attention_kernel,
                         cudaFuncAttributeMaxDynamicSharedMemorySize, ATT_SMEM_BYTES);

    // rope tables + combined weights/biases (exact fp32)
    rope_kernel<<<(S_LEN * HALF_W + 255) / 256, 256>>>(rc, rs);
    sgemm_nn_kernel<<<dim3(8, 8), 256>>>(Wv, v_w, wcv, W_DIM, W_DIM, W_DIM);
    sgemm_nn_kernel<<<dim3(8, 8), 256>>>(out_w, mo_w, wco, W_DIM, W_DIM, W_DIM);
    bias_combine<<<(W_DIM * 32) / 256, 256>>>(Wv, v_b, bv, bcv);
    bias_combine<<<(W_DIM * 32) / 256, 256>>>(out_w, mo_b, out_b, bco);

    dim3 big(W_DIM / 64, M_ROWS / 128);   // (16, 194)

    // stage 1: q/k projections fused with rotary; v path fully combined
    gemm_bf16s_kernel<1><<<big, 256, GEMM_SMEM_BYTES>>>(tensor, q_w, q_b, q1,
                                                        M_ROWS, W_DIM, W_DIM, rc, rs);
    gemm_bf16s_kernel<1><<<big, 256, GEMM_SMEM_BYTES>>>(tensor, k_w, k_b, k1,
                                                        M_ROWS, W_DIM, W_DIM, rc, rs);
    gemm_bf16s_kernel<0><<<big, 256, GEMM_SMEM_BYTES>>>(tensor, wcv, bcv, v2,
                                                        M_ROWS, W_DIM, W_DIM, nullptr, nullptr);

    // stage 2: in_proj on rotated q/k
    gemm_bf16s_kernel<0><<<big, 256, GEMM_SMEM_BYTES>>>(q1, in_w, in_b, q2,
                                                        M_ROWS, W_DIM, W_DIM, nullptr, nullptr);
    gemm_bf16s_kernel<0><<<big, 256, GEMM_SMEM_BYTES>>>(k1, in_w + (size_t)W_DIM * W_DIM,
                                                        in_b + W_DIM, k2,
                                                        M_ROWS, W_DIM, W_DIM, nullptr, nullptr);

    // attention
    attention_kernel<<<B_DIM * H_NUM, 128, ATT_SMEM_BYTES>>>(q2, k2, v2, mask, ob);

    // fused output projection (mha_out then out combined)
    gemm_bf16s_kernel<0><<<big, 256, GEMM_SMEM_BYTES>>>(ob, wco, bco, out,
                                                        M_ROWS, W_DIM, W_DIM, nullptr, nullptr);
}